// round 1
// baseline (speedup 1.0000x reference)
#include <cuda_runtime.h>
#include <cuda_bf16.h>
#include <cstdint>

// Problem constants
#define B_WIN 256
#define NTOK  144
#define DIM   384
#define HEADS 12
#define HD    32
#define QKV_N 1152
#define MROWS (B_WIN*NTOK)        // 36864
#define QSCALE 0.17677669529663689f   // 32^-0.5

// Scratch (static device globals; allocation-free)
__device__ float g_q[14155776];   // (b*12+h, i, d)  256*12*144*32
__device__ float g_k[14155776];
__device__ float g_v[14155776];
__device__ float g_att[14155776]; // (b*144+i, h*32+d) = (36864, 384)

// ---------------------------------------------------------------------------
// GEMM 1: qkv = x(36864x384) @ w_qkv(384x1152) + b_qkv, scatter to g_q/k/v
// BM=128 BN=128 BK=16, 256 threads, 8x8 microtiles
// ---------------------------------------------------------------------------
__global__ __launch_bounds__(256, 2)
void gemm_qkv_kernel(const float* __restrict__ A, const float* __restrict__ B,
                     const float* __restrict__ bias)
{
    __shared__ float As[16][128];
    __shared__ float Bs[16][128];

    const int bm = blockIdx.y * 128;
    const int bn = blockIdx.x * 128;
    const int tid = threadIdx.x;
    const int warp = tid >> 5, lane = tid & 31;
    const int wm = warp >> 2, wn = warp & 3;      // 2 x 4 warps
    const int lm = lane >> 2, ln = lane & 3;      // 8 x 4 lanes
    const int m0 = wm * 64 + lm * 8;
    const int n0 = wn * 32 + ln * 8;

    const int arow = tid >> 2, acol = (tid & 3) * 4;
    const int brow = tid >> 5, bcol = (tid & 31) * 4;

    float acc[8][8];
#pragma unroll
    for (int r = 0; r < 8; r++)
#pragma unroll
        for (int c = 0; c < 8; c++) acc[r][c] = 0.f;

    for (int k0 = 0; k0 < DIM; k0 += 16) {
#pragma unroll
        for (int it = 0; it < 2; it++) {
            int r = arow + it * 64;
            float4 av = *(const float4*)(A + (size_t)(bm + r) * DIM + k0 + acol);
            As[acol + 0][r] = av.x; As[acol + 1][r] = av.y;
            As[acol + 2][r] = av.z; As[acol + 3][r] = av.w;
        }
#pragma unroll
        for (int it = 0; it < 2; it++) {
            int r = brow + it * 8;
            *(float4*)(&Bs[r][bcol]) =
                *(const float4*)(B + (size_t)(k0 + r) * QKV_N + bn + bcol);
        }
        __syncthreads();
#pragma unroll
        for (int k = 0; k < 16; k++) {
            float af[8], bf[8];
            *(float4*)(af)     = *(const float4*)(&As[k][m0]);
            *(float4*)(af + 4) = *(const float4*)(&As[k][m0 + 4]);
            *(float4*)(bf)     = *(const float4*)(&Bs[k][n0]);
            *(float4*)(bf + 4) = *(const float4*)(&Bs[k][n0 + 4]);
#pragma unroll
            for (int r = 0; r < 8; r++)
#pragma unroll
                for (int c = 0; c < 8; c++) acc[r][c] += af[r] * bf[c];
        }
        __syncthreads();
    }

    // Epilogue: + bias, scale q, scatter into (b,h,i,d) layout
#pragma unroll
    for (int r = 0; r < 8; r++) {
        int row = bm + m0 + r;
        int b = row / NTOK, i = row - b * NTOK;
#pragma unroll
        for (int c = 0; c < 8; c++) {
            int col = bn + n0 + c;
            float val = acc[r][c] + bias[col];
            int s = col / DIM;
            int rem = col - s * DIM;
            int hh = rem >> 5, d = rem & 31;
            if (s == 0) val *= QSCALE;
            float* dst = (s == 0) ? g_q : (s == 1 ? g_k : g_v);
            dst[((size_t)(b * HEADS + hh) * NTOK + i) * HD + d] = val;
        }
    }
}

// ---------------------------------------------------------------------------
// Fused attention per (b,h): S = QK^T + bias + mask, softmax, O = S V
// 512 threads, dynamic smem ~151KB
// ---------------------------------------------------------------------------
#define SS_LD 148   // padded row stride for S (16B aligned, staggers banks)

__global__ __launch_bounds__(512, 1)
void attn_kernel(const float* __restrict__ mask,
                 const float* __restrict__ bias_table,
                 const int*   __restrict__ pos_idx)
{
    extern __shared__ float sm[];
    float* sQt = sm;                  // [32][144]  (d-major, transposed)
    float* sKt = sQt + 32 * 144;      // [32][144]
    float* sV  = sKt + 32 * 144;      // [144][32]
    float* sS  = sV  + 144 * 32;      // [144][SS_LD]
    float* sB  = sS  + 144 * SS_LD;   // [2592]

    const int bh = blockIdx.x;
    const int b = bh / HEADS, h = bh - b * HEADS;
    const int g  = b >> 5;        // b / TOW
    const int t  = b & 31;        // b % TOW
    const int mw = b & 7;         // b % nW

    const int tid = threadIdx.x;
    const int wid = tid >> 5, lane = tid & 31;

    const float* qb = g_q + (size_t)bh * (NTOK * HD);
    const float* kb = g_k + (size_t)bh * (NTOK * HD);
    const float* vb = g_v + (size_t)bh * (NTOK * HD);

    // Load Q,K (transposed), V (natural)
    for (int idx = tid; idx < NTOK * 8; idx += 512) {
        int i = idx >> 3;
        int d0 = (idx & 7) * 4;
        float4 qv = *(const float4*)(qb + i * HD + d0);
        float4 kv = *(const float4*)(kb + i * HD + d0);
        float4 vv = *(const float4*)(vb + i * HD + d0);
        sQt[(d0 + 0) * 144 + i] = qv.x; sQt[(d0 + 1) * 144 + i] = qv.y;
        sQt[(d0 + 2) * 144 + i] = qv.z; sQt[(d0 + 3) * 144 + i] = qv.w;
        sKt[(d0 + 0) * 144 + i] = kv.x; sKt[(d0 + 1) * 144 + i] = kv.y;
        sKt[(d0 + 2) * 144 + i] = kv.z; sKt[(d0 + 3) * 144 + i] = kv.w;
        *(float4*)(sV + i * HD + d0) = vv;
    }
    // Bias cache: bias(i,j) = sB[(i%18)*144 + j]
    for (int s = tid; s < 2592; s += 512)
        sB[s] = bias_table[(size_t)pos_idx[8 * s + g] * (32 * HEADS) + t * HEADS + h];
    __syncthreads();

    // ---- Scores: 36x36 tiles of 4x4, patches of 4(i)x8(j) tiles per warp ----
    const int li = lane & 3;     // i-tile within patch
    const int lj = lane >> 2;    // j-tile within patch
    for (int p = wid; p < 45; p += 16) {
        int pi = p / 5, pj = p - pi * 5;
        int ti = pi * 4 + li;          // < 36
        int tj = pj * 8 + lj;          // may be >= 36
        if (tj >= 36) continue;
        int i0 = ti * 4, j0 = tj * 4;
        float acc[4][4];
#pragma unroll
        for (int r = 0; r < 4; r++)
#pragma unroll
            for (int c = 0; c < 4; c++) acc[r][c] = 0.f;
#pragma unroll
        for (int d = 0; d < HD; d++) {
            float4 qv = *(const float4*)(sQt + d * 144 + i0);
            float4 kv = *(const float4*)(sKt + d * 144 + j0);
            float qa[4] = {qv.x, qv.y, qv.z, qv.w};
            float ka[4] = {kv.x, kv.y, kv.z, kv.w};
#pragma unroll
            for (int r = 0; r < 4; r++)
#pragma unroll
                for (int c = 0; c < 4; c++) acc[r][c] += qa[r] * ka[c];
        }
#pragma unroll
        for (int r = 0; r < 4; r++) {
            int i = i0 + r;
            int im = i % 18;
            float4 mv = *(const float4*)(mask + ((size_t)mw * 144 + i) * 144 + j0);
            float4 bv = *(const float4*)(sB + im * 144 + j0);
            float4 sv;
            sv.x = acc[r][0] + bv.x + mv.x;
            sv.y = acc[r][1] + bv.y + mv.y;
            sv.z = acc[r][2] + bv.z + mv.z;
            sv.w = acc[r][3] + bv.w + mv.w;
            *(float4*)(sS + i * SS_LD + j0) = sv;
        }
    }
    __syncthreads();

    // ---- Softmax: one warp per row (16 warps, 9 rows each) ----
    for (int i = wid; i < NTOK; i += 16) {
        float* row = sS + i * SS_LD;
        float m = -1e30f;
        for (int j = lane; j < NTOK; j += 32) m = fmaxf(m, row[j]);
#pragma unroll
        for (int o = 16; o > 0; o >>= 1) m = fmaxf(m, __shfl_xor_sync(0xffffffffu, m, o));
        float sum = 0.f;
        for (int j = lane; j < NTOK; j += 32) {
            float e = __expf(row[j] - m);
            row[j] = e;
            sum += e;
        }
#pragma unroll
        for (int o = 16; o > 0; o >>= 1) sum += __shfl_xor_sync(0xffffffffu, sum, o);
        float inv = 1.f / sum;
        for (int j = lane; j < NTOK; j += 32) row[j] *= inv;
    }
    __syncthreads();

    // ---- O = P @ V: 36 i-tiles x 8 d-tiles of 4x4 (288 threads) ----
    if (tid < 288) {
        int ti = tid >> 3, dq = tid & 7;
        int i0 = ti * 4, d0 = dq * 4;
        float acc[4][4];
#pragma unroll
        for (int r = 0; r < 4; r++)
#pragma unroll
            for (int c = 0; c < 4; c++) acc[r][c] = 0.f;
        for (int j0 = 0; j0 < NTOK; j0 += 4) {
            float pf[4][4];
#pragma unroll
            for (int r = 0; r < 4; r++) {
                float4 pv = *(const float4*)(sS + (i0 + r) * SS_LD + j0);
                pf[r][0] = pv.x; pf[r][1] = pv.y; pf[r][2] = pv.z; pf[r][3] = pv.w;
            }
#pragma unroll
            for (int jj = 0; jj < 4; jj++) {
                float4 vv = *(const float4*)(sV + (j0 + jj) * HD + d0);
                float vf[4] = {vv.x, vv.y, vv.z, vv.w};
#pragma unroll
                for (int r = 0; r < 4; r++)
#pragma unroll
                    for (int c = 0; c < 4; c++) acc[r][c] += pf[r][jj] * vf[c];
            }
        }
#pragma unroll
        for (int r = 0; r < 4; r++) {
            float4 ov = make_float4(acc[r][0], acc[r][1], acc[r][2], acc[r][3]);
            *(float4*)(g_att + ((size_t)b * NTOK + i0 + r) * DIM + h * HD + d0) = ov;
        }
    }
}

// ---------------------------------------------------------------------------
// GEMM 2: out = g_att(36864x384) @ w_out(384x384) + b_out
// ---------------------------------------------------------------------------
__global__ __launch_bounds__(256, 2)
void gemm_out_kernel(const float* __restrict__ B, const float* __restrict__ bias,
                     float* __restrict__ out)
{
    __shared__ float As[16][128];
    __shared__ float Bs[16][128];

    const float* A = g_att;
    const int bm = blockIdx.y * 128;
    const int bn = blockIdx.x * 128;
    const int tid = threadIdx.x;
    const int warp = tid >> 5, lane = tid & 31;
    const int wm = warp >> 2, wn = warp & 3;
    const int lm = lane >> 2, ln = lane & 3;
    const int m0 = wm * 64 + lm * 8;
    const int n0 = wn * 32 + ln * 8;

    const int arow = tid >> 2, acol = (tid & 3) * 4;
    const int brow = tid >> 5, bcol = (tid & 31) * 4;

    float acc[8][8];
#pragma unroll
    for (int r = 0; r < 8; r++)
#pragma unroll
        for (int c = 0; c < 8; c++) acc[r][c] = 0.f;

    for (int k0 = 0; k0 < DIM; k0 += 16) {
#pragma unroll
        for (int it = 0; it < 2; it++) {
            int r = arow + it * 64;
            float4 av = *(const float4*)(A + (size_t)(bm + r) * DIM + k0 + acol);
            As[acol + 0][r] = av.x; As[acol + 1][r] = av.y;
            As[acol + 2][r] = av.z; As[acol + 3][r] = av.w;
        }
#pragma unroll
        for (int it = 0; it < 2; it++) {
            int r = brow + it * 8;
            *(float4*)(&Bs[r][bcol]) =
                *(const float4*)(B + (size_t)(k0 + r) * DIM + bn + bcol);
        }
        __syncthreads();
#pragma unroll
        for (int k = 0; k < 16; k++) {
            float af[8], bf[8];
            *(float4*)(af)     = *(const float4*)(&As[k][m0]);
            *(float4*)(af + 4) = *(const float4*)(&As[k][m0 + 4]);
            *(float4*)(bf)     = *(const float4*)(&Bs[k][n0]);
            *(float4*)(bf + 4) = *(const float4*)(&Bs[k][n0 + 4]);
#pragma unroll
            for (int r = 0; r < 8; r++)
#pragma unroll
                for (int c = 0; c < 8; c++) acc[r][c] += af[r] * bf[c];
        }
        __syncthreads();
    }

#pragma unroll
    for (int r = 0; r < 8; r++) {
        int row = bm + m0 + r;
#pragma unroll
        for (int cq = 0; cq < 2; cq++) {
            int col = bn + n0 + cq * 4;
            float4 ov;
            ov.x = acc[r][cq * 4 + 0] + bias[col + 0];
            ov.y = acc[r][cq * 4 + 1] + bias[col + 1];
            ov.z = acc[r][cq * 4 + 2] + bias[col + 2];
            ov.w = acc[r][cq * 4 + 3] + bias[col + 3];
            *(float4*)(out + (size_t)row * DIM + col) = ov;
        }
    }
}

// ---------------------------------------------------------------------------
extern "C" void kernel_launch(void* const* d_in, const int* in_sizes, int n_in,
                              void* d_out, int out_size)
{
    const float* x          = (const float*)d_in[0];
    const float* mask       = (const float*)d_in[1];
    const float* w_qkv      = (const float*)d_in[2];
    const float* b_qkv      = (const float*)d_in[3];
    const float* w_out      = (const float*)d_in[4];
    const float* b_out      = (const float*)d_in[5];
    const float* bias_table = (const float*)d_in[6];
    const int*   pos_idx    = (const int*)d_in[7];
    float* out = (float*)d_out;

    const int smem_attn = (32 * 144 * 2 + 144 * 32 + 144 * SS_LD + 2592) * 4;
    cudaFuncSetAttribute(attn_kernel, cudaFuncAttributeMaxDynamicSharedMemorySize,
                         smem_attn);

    gemm_qkv_kernel<<<dim3(QKV_N / 128, MROWS / 128), 256>>>(x, w_qkv, b_qkv);
    attn_kernel<<<B_WIN * HEADS, 512, smem_attn>>>(mask, bias_table, pos_idx);
    gemm_out_kernel<<<dim3(DIM / 128, MROWS / 128), 256>>>(w_out, b_out, out);
}